// round 4
// baseline (speedup 1.0000x reference)
#include <cuda_runtime.h>

#define BB 4
#define SS 1024
#define DDIM 512
#define HH 8
#define DH 64
#define RP (2*SS-1)   // 2047

// Output layout (tuple concatenated, float32):
//   out      [B,S,D]      @ 0
//   attn     [B,H,S,S]    @ OFF_ATTN
//   content  [B,H,S,S]    @ OFF_CONTENT
//   pos      [B,H,S,S]    @ OFF_POS   (already relative-shifted)
#define N_OUT  ((size_t)BB*SS*DDIM)          // 2,097,152
#define N_SC   ((size_t)BB*HH*SS*SS)         // 33,554,432
#define OFF_ATTN     (N_OUT)
#define OFF_CONTENT  (N_OUT + N_SC)
#define OFF_POS      (N_OUT + 2*N_SC)

// Scratch (allocation-free: device globals)
__device__ float g_q[BB*SS*DDIM];
__device__ float g_k[BB*SS*DDIM];
__device__ float g_v[BB*SS*DDIM];
__device__ float g_oh[BB*SS*DDIM];
__device__ float g_rel[RP*DH];

// ---------------------------------------------------------------------------
// C[M,N] = A[M,K] @ W[N,K]^T + bias     (M=4096, N=512, K=512)
// 64x64 block tile, 256 threads, 4x4 strided micro-tile.
// ---------------------------------------------------------------------------
__global__ void proj_gemm(const float* __restrict__ A, const float* __restrict__ W,
                          const float* __restrict__ bias, float* __restrict__ C) {
    const int K = DDIM, N = DDIM;
    __shared__ float As[64][17];
    __shared__ float Ws[64][17];
    const int tid = threadIdx.x;
    const int tx = tid & 15, ty = tid >> 4;
    const int m0 = blockIdx.y * 64, n0 = blockIdx.x * 64;
    const int lrow = tid >> 2, lq = (tid & 3) << 2;

    float acc[4][4];
#pragma unroll
    for (int i = 0; i < 4; i++)
#pragma unroll
        for (int j = 0; j < 4; j++) acc[i][j] = 0.f;

    for (int k0 = 0; k0 < K; k0 += 16) {
        float4 a4 = *(const float4*)&A[(size_t)(m0 + lrow) * K + k0 + lq];
        float4 w4 = *(const float4*)&W[(size_t)(n0 + lrow) * K + k0 + lq];
        As[lrow][lq+0] = a4.x; As[lrow][lq+1] = a4.y; As[lrow][lq+2] = a4.z; As[lrow][lq+3] = a4.w;
        Ws[lrow][lq+0] = w4.x; Ws[lrow][lq+1] = w4.y; Ws[lrow][lq+2] = w4.z; Ws[lrow][lq+3] = w4.w;
        __syncthreads();
#pragma unroll
        for (int kk = 0; kk < 16; kk++) {
            float av[4], wv[4];
#pragma unroll
            for (int i = 0; i < 4; i++) av[i] = As[ty + 16*i][kk];
#pragma unroll
            for (int j = 0; j < 4; j++) wv[j] = Ws[tx + 16*j][kk];
#pragma unroll
            for (int i = 0; i < 4; i++)
#pragma unroll
                for (int j = 0; j < 4; j++) acc[i][j] += av[i] * wv[j];
        }
        __syncthreads();
    }
#pragma unroll
    for (int i = 0; i < 4; i++)
#pragma unroll
        for (int j = 0; j < 4; j++) {
            int m = m0 + ty + 16*i, n = n0 + tx + 16*j;
            C[(size_t)m * N + n] = acc[i][j] + bias[n];
        }
}

// ---------------------------------------------------------------------------
// rel[r,n] = sum_k pos_emb[r,k] * Wp[n,k] + bp[n]   (r<2047, n,k<64)
// ---------------------------------------------------------------------------
__global__ void rel_proj(const float* __restrict__ pos_emb, const float* __restrict__ Wp,
                         const float* __restrict__ bp, float* __restrict__ rel) {
    __shared__ float pe[DH];
    __shared__ float wps[DH][DH + 1];
    const int r = blockIdx.x;
    const int tid = threadIdx.x;
    pe[tid] = pos_emb[(size_t)r * DH + tid];
#pragma unroll
    for (int j = 0; j < DH; j++) wps[j][tid] = Wp[(size_t)j * DH + tid];
    __syncthreads();
    float acc = bp[tid];
#pragma unroll 8
    for (int k = 0; k < DH; k++) acc += pe[k] * wps[tid][k];
    rel[(size_t)r * DH + tid] = acc;
}

// ---------------------------------------------------------------------------
// Fused content + (pre-shifted) positional score.
//   content[z,s,t] = sum_d q[z,s,d]*k[z,t,d]
//   pos[z,s,t]     = sum_d q[z,s,d]*rel[t-s+S-1,d]   (skew trick collapsed)
// Block = 64x64 (s,t) tile for one z=(b,h). rel window = 127 rows, in-bounds
// by construction for 64-aligned tiles.
// ---------------------------------------------------------------------------
__global__ void score_kernel(const float* __restrict__ Qp, const float* __restrict__ Kp,
                             const float* __restrict__ rel,
                             float* __restrict__ outc, float* __restrict__ outp) {
    extern __shared__ float sm[];
    float (*qs)[65] = (float(*)[65])sm;
    float (*ks)[65] = (float(*)[65])(sm + 64 * 65);
    float (*rs)[65] = (float(*)[65])(sm + 2 * 64 * 65);

    const int z = blockIdx.z;
    const int b = z >> 3, h = z & 7;
    const int s0 = blockIdx.y * 64, t0 = blockIdx.x * 64;
    const int tid = threadIdx.x, tx = tid & 15, ty = tid >> 4;

    // load q, k tiles: 64 rows x 64 floats each
#pragma unroll
    for (int it = 0; it < 4; it++) {
        int idx = tid + 256 * it;
        int row = idx >> 4, c = (idx & 15) << 2;
        float4 v4 = *(const float4*)&Qp[((size_t)(b * SS + s0 + row)) * DDIM + h * DH + c];
        qs[row][c+0] = v4.x; qs[row][c+1] = v4.y; qs[row][c+2] = v4.z; qs[row][c+3] = v4.w;
        v4 = *(const float4*)&Kp[((size_t)(b * SS + t0 + row)) * DDIM + h * DH + c];
        ks[row][c+0] = v4.x; ks[row][c+1] = v4.y; ks[row][c+2] = v4.z; ks[row][c+3] = v4.w;
    }
    // rel window: rows baser .. baser+126  (= t0-s0+S-1-63 ... +63)
    const int baser = t0 - s0 + SS - 1 - 63;
    for (int idx = tid; idx < 127 * 16; idx += 256) {
        int row = idx >> 4, c = (idx & 15) << 2;
        float4 v4 = *(const float4*)&rel[(size_t)(baser + row) * DH + c];
        rs[row][c+0] = v4.x; rs[row][c+1] = v4.y; rs[row][c+2] = v4.z; rs[row][c+3] = v4.w;
    }
    __syncthreads();

    float accC[4][4], accP[4][4];
#pragma unroll
    for (int i = 0; i < 4; i++)
#pragma unroll
        for (int j = 0; j < 4; j++) { accC[i][j] = 0.f; accP[i][j] = 0.f; }

    const int rbase = tx - ty + 15;   // smem rel index for (j-i) = -3
#pragma unroll 8
    for (int d = 0; d < 64; d++) {
        float a[4], kv[4], rl[7];
#pragma unroll
        for (int i = 0; i < 4; i++) a[i] = qs[ty + 16*i][d];
#pragma unroll
        for (int j = 0; j < 4; j++) kv[j] = ks[tx + 16*j][d];
#pragma unroll
        for (int m = 0; m < 7; m++) rl[m] = rs[rbase + 16*m][d];
#pragma unroll
        for (int i = 0; i < 4; i++)
#pragma unroll
            for (int j = 0; j < 4; j++) {
                accC[i][j] += a[i] * kv[j];
                accP[i][j] += a[i] * rl[j - i + 3];
            }
    }

#pragma unroll
    for (int i = 0; i < 4; i++)
#pragma unroll
        for (int j = 0; j < 4; j++) {
            int s = s0 + ty + 16*i, t = t0 + tx + 16*j;
            size_t o = ((size_t)z * SS + s) * SS + t;
            outc[o] = accC[i][j];
            outp[o] = accP[i][j];
        }
}

// ---------------------------------------------------------------------------
// Softmax over rows of (content + pos) / sqrt(D). One block per row.
// ---------------------------------------------------------------------------
__global__ void softmax_kernel(const float* __restrict__ outc, const float* __restrict__ outp,
                               float* __restrict__ attn) {
    const size_t row = blockIdx.x;
    const float* c = outc + row * SS;
    const float* p = outp + row * SS;
    const int tid = threadIdx.x;
    const int lane = tid & 31, wid = tid >> 5;
    const float scale = 0.044194173824159216f; // 1/sqrt(512)

    float v[4], m = -3.4e38f;
#pragma unroll
    for (int u = 0; u < 4; u++) {
        int t = tid + 256 * u;
        v[u] = (c[t] + p[t]) * scale;
        m = fmaxf(m, v[u]);
    }
#pragma unroll
    for (int o = 16; o > 0; o >>= 1) m = fmaxf(m, __shfl_xor_sync(0xffffffffu, m, o));
    __shared__ float redm[8], reds[8];
    if (lane == 0) redm[wid] = m;
    __syncthreads();
    if (tid == 0) {
        float mm = redm[0];
#pragma unroll
        for (int i = 1; i < 8; i++) mm = fmaxf(mm, redm[i]);
        redm[0] = mm;
    }
    __syncthreads();
    m = redm[0];

    float s = 0.f;
#pragma unroll
    for (int u = 0; u < 4; u++) { v[u] = __expf(v[u] - m); s += v[u]; }
#pragma unroll
    for (int o = 16; o > 0; o >>= 1) s += __shfl_xor_sync(0xffffffffu, s, o);
    if (lane == 0) reds[wid] = s;
    __syncthreads();
    if (tid == 0) {
        float ss = 0.f;
#pragma unroll
        for (int i = 0; i < 8; i++) ss += reds[i];
        reds[0] = ss;
    }
    __syncthreads();
    const float inv = 1.f / reds[0];
#pragma unroll
    for (int u = 0; u < 4; u++) attn[row * SS + tid + 256 * u] = v[u] * inv;
}

// ---------------------------------------------------------------------------
// out_h[b,s,h*64+d] = sum_t attn[z,s,t] * v[b,t,h*64+d]
// Block = 64 s-rows x full dh=64 for one z.
// ---------------------------------------------------------------------------
__global__ void av_kernel(const float* __restrict__ attn, const float* __restrict__ Vp,
                          float* __restrict__ Oh) {
    __shared__ float as_[64][65];
    __shared__ float vs[64][65];
    const int z = blockIdx.y;
    const int b = z >> 3, h = z & 7;
    const int s0 = blockIdx.x * 64;
    const int tid = threadIdx.x, tx = tid & 15, ty = tid >> 4;

    float acc[4][4];
#pragma unroll
    for (int i = 0; i < 4; i++)
#pragma unroll
        for (int j = 0; j < 4; j++) acc[i][j] = 0.f;

    for (int t0 = 0; t0 < SS; t0 += 64) {
#pragma unroll
        for (int it = 0; it < 4; it++) {
            int idx = tid + 256 * it;
            int row = idx >> 4, c = (idx & 15) << 2;
            float4 a4 = *(const float4*)&attn[((size_t)z * SS + s0 + row) * SS + t0 + c];
            as_[row][c+0] = a4.x; as_[row][c+1] = a4.y; as_[row][c+2] = a4.z; as_[row][c+3] = a4.w;
            float4 v4 = *(const float4*)&Vp[((size_t)(b * SS + t0 + row)) * DDIM + h * DH + c];
            vs[row][c+0] = v4.x; vs[row][c+1] = v4.y; vs[row][c+2] = v4.z; vs[row][c+3] = v4.w;
        }
        __syncthreads();
#pragma unroll 8
        for (int tt = 0; tt < 64; tt++) {
            float a[4], vv[4];
#pragma unroll
            for (int i = 0; i < 4; i++) a[i] = as_[ty + 16*i][tt];
#pragma unroll
            for (int j = 0; j < 4; j++) vv[j] = vs[tt][tx + 16*j];
#pragma unroll
            for (int i = 0; i < 4; i++)
#pragma unroll
                for (int j = 0; j < 4; j++) acc[i][j] += a[i] * vv[j];
        }
        __syncthreads();
    }
#pragma unroll
    for (int i = 0; i < 4; i++)
#pragma unroll
        for (int j = 0; j < 4; j++)
            Oh[((size_t)(b * SS + s0 + ty + 16*i)) * DDIM + h * DH + tx + 16*j] = acc[i][j];
}

// ---------------------------------------------------------------------------
extern "C" void kernel_launch(void* const* d_in, const int* in_sizes, int n_in,
                              void* d_out, int out_size) {
    const float* query   = (const float*)d_in[0];
    const float* key     = (const float*)d_in[1];
    const float* value   = (const float*)d_in[2];
    const float* pos_emb = (const float*)d_in[3];
    const float* Wq = (const float*)d_in[4];
    const float* bq = (const float*)d_in[5];
    const float* Wk = (const float*)d_in[6];
    const float* bk = (const float*)d_in[7];
    const float* Wv = (const float*)d_in[8];
    const float* bv = (const float*)d_in[9];
    const float* Wo = (const float*)d_in[10];
    const float* bo = (const float*)d_in[11];
    const float* Wp = (const float*)d_in[12];
    const float* bp = (const float*)d_in[13];
    float* out = (float*)d_out;

    float *gq, *gk, *gv, *goh, *grel;
    cudaGetSymbolAddress((void**)&gq, g_q);
    cudaGetSymbolAddress((void**)&gk, g_k);
    cudaGetSymbolAddress((void**)&gv, g_v);
    cudaGetSymbolAddress((void**)&goh, g_oh);
    cudaGetSymbolAddress((void**)&grel, g_rel);

    const int score_smem = (2 * 64 * 65 + 127 * 65) * (int)sizeof(float); // 66300 B
    cudaFuncSetAttribute(score_kernel, cudaFuncAttributeMaxDynamicSharedMemorySize, score_smem);

    dim3 gproj(DDIM / 64, (BB * SS) / 64);   // (8, 64)
    proj_gemm<<<gproj, 256>>>(query, Wq, bq, gq);
    proj_gemm<<<gproj, 256>>>(key,   Wk, bk, gk);
    proj_gemm<<<gproj, 256>>>(value, Wv, bv, gv);
    rel_proj<<<RP, DH>>>(pos_emb, Wp, bp, grel);

    score_kernel<<<dim3(SS / 64, SS / 64, BB * HH), 256, score_smem>>>(
        gq, gk, grel, out + OFF_CONTENT, out + OFF_POS);

    softmax_kernel<<<BB * HH * SS, 256>>>(out + OFF_CONTENT, out + OFF_POS, out + OFF_ATTN);

    av_kernel<<<dim3(SS / 64, BB * HH), 256>>>(out + OFF_ATTN, gv, goh);

    proj_gemm<<<gproj, 256>>>(goh, Wo, bo, out);
}

// round 5
// speedup vs baseline: 1.0806x; 1.0806x over previous
#include <cuda_runtime.h>

#define BB 4
#define SS 1024
#define DDIM 512
#define HH 8
#define DH 64
#define RP (2*SS-1)   // 2047

// Output layout (tuple concatenated, float32):
//   out      [B,S,D]      @ 0
//   attn     [B,H,S,S]    @ OFF_ATTN
//   content  [B,H,S,S]    @ OFF_CONTENT
//   pos      [B,H,S,S]    @ OFF_POS   (already relative-shifted)
#define N_OUT  ((size_t)BB*SS*DDIM)          // 2,097,152
#define N_SC   ((size_t)BB*HH*SS*SS)         // 33,554,432
#define OFF_ATTN     (N_OUT)
#define OFF_CONTENT  (N_OUT + N_SC)
#define OFF_POS      (N_OUT + 2*N_SC)

// Scratch (allocation-free: device globals)
__device__ float g_q[BB*SS*DDIM];
__device__ float g_k[BB*SS*DDIM];
__device__ float g_v[BB*SS*DDIM];
__device__ float g_oh[BB*SS*DDIM];
__device__ float g_rel[RP*DH];

// ---------------------------------------------------------------------------
// C[M,N] = A[M,K] @ W[N,K]^T + bias     (M=4096, N=512, K=512)
// 64x64 block tile, 256 threads, 4x4 strided micro-tile.
// Inner loop vectorized: LDS.128 along k (row stride padded to 20 floats).
// ---------------------------------------------------------------------------
__global__ void proj_gemm(const float* __restrict__ A, const float* __restrict__ W,
                          const float* __restrict__ bias, float* __restrict__ C) {
    const int K = DDIM, N = DDIM;
    __shared__ float As[64][20];
    __shared__ float Ws[64][20];
    const int tid = threadIdx.x;
    const int tx = tid & 15, ty = tid >> 4;
    const int m0 = blockIdx.y * 64, n0 = blockIdx.x * 64;
    const int lrow = tid >> 2, lq = (tid & 3) << 2;

    float acc[4][4];
#pragma unroll
    for (int i = 0; i < 4; i++)
#pragma unroll
        for (int j = 0; j < 4; j++) acc[i][j] = 0.f;

    for (int k0 = 0; k0 < K; k0 += 16) {
        float4 a4 = *(const float4*)&A[(size_t)(m0 + lrow) * K + k0 + lq];
        float4 w4 = *(const float4*)&W[(size_t)(n0 + lrow) * K + k0 + lq];
        *(float4*)&As[lrow][lq] = a4;
        *(float4*)&Ws[lrow][lq] = w4;
        __syncthreads();
#pragma unroll
        for (int kk0 = 0; kk0 < 16; kk0 += 4) {
            float a_[4][4], w_[4][4];
#pragma unroll
            for (int i = 0; i < 4; i++) {
                float4 t = *(const float4*)&As[ty + 16*i][kk0];
                a_[i][0] = t.x; a_[i][1] = t.y; a_[i][2] = t.z; a_[i][3] = t.w;
            }
#pragma unroll
            for (int j = 0; j < 4; j++) {
                float4 t = *(const float4*)&Ws[tx + 16*j][kk0];
                w_[j][0] = t.x; w_[j][1] = t.y; w_[j][2] = t.z; w_[j][3] = t.w;
            }
#pragma unroll
            for (int c = 0; c < 4; c++)
#pragma unroll
                for (int i = 0; i < 4; i++)
#pragma unroll
                    for (int j = 0; j < 4; j++) acc[i][j] += a_[i][c] * w_[j][c];
        }
        __syncthreads();
    }
#pragma unroll
    for (int i = 0; i < 4; i++)
#pragma unroll
        for (int j = 0; j < 4; j++) {
            int m = m0 + ty + 16*i, n = n0 + tx + 16*j;
            C[(size_t)m * N + n] = acc[i][j] + bias[n];
        }
}

// ---------------------------------------------------------------------------
// rel[r,n] = sum_k pos_emb[r,k] * Wp[n,k] + bp[n]   (r<2047, n,k<64)
// ---------------------------------------------------------------------------
__global__ void rel_proj(const float* __restrict__ pos_emb, const float* __restrict__ Wp,
                         const float* __restrict__ bp, float* __restrict__ rel) {
    __shared__ float pe[DH];
    __shared__ float wps[DH][DH + 1];
    const int r = blockIdx.x;
    const int tid = threadIdx.x;
    pe[tid] = pos_emb[(size_t)r * DH + tid];
#pragma unroll
    for (int j = 0; j < DH; j++) wps[j][tid] = Wp[(size_t)j * DH + tid];
    __syncthreads();
    float acc = bp[tid];
#pragma unroll 8
    for (int k = 0; k < DH; k++) acc += pe[k] * wps[tid][k];
    rel[(size_t)r * DH + tid] = acc;
}

// ---------------------------------------------------------------------------
// Fused content + (pre-shifted) positional score.
//   content[z,s,t] = sum_d q[z,s,d]*k[z,t,d]
//   pos[z,s,t]     = sum_d q[z,s,d]*rel[t-s+S-1,d]   (skew trick collapsed)
// Block = 64x64 (s,t) tile for one z=(b,h). rel window = 127 rows, in-bounds
// by construction for 64-aligned tiles. Inner loop: LDS.128 along d,
// 15 vector loads per 128 FFMA. Rows padded to 68 floats (16B-aligned).
// ---------------------------------------------------------------------------
__global__ void __launch_bounds__(256, 2)
score_kernel(const float* __restrict__ Qp, const float* __restrict__ Kp,
             const float* __restrict__ rel,
             float* __restrict__ outc, float* __restrict__ outp) {
    extern __shared__ float sm[];
    float (*qs)[68] = (float(*)[68])sm;
    float (*ks)[68] = (float(*)[68])(sm + 64 * 68);
    float (*rs)[68] = (float(*)[68])(sm + 2 * 64 * 68);

    const int z = blockIdx.z;
    const int b = z >> 3, h = z & 7;
    const int s0 = blockIdx.y * 64, t0 = blockIdx.x * 64;
    const int tid = threadIdx.x, tx = tid & 15, ty = tid >> 4;

    // load q, k tiles: 64 rows x 64 floats each (STS.128, coalesced)
#pragma unroll
    for (int it = 0; it < 4; it++) {
        int idx = tid + 256 * it;
        int row = idx >> 4, c = (idx & 15) << 2;
        *(float4*)&qs[row][c] =
            *(const float4*)&Qp[((size_t)(b * SS + s0 + row)) * DDIM + h * DH + c];
        *(float4*)&ks[row][c] =
            *(const float4*)&Kp[((size_t)(b * SS + t0 + row)) * DDIM + h * DH + c];
    }
    // rel window: rows baser .. baser+126  (= t0-s0+S-1-63 ... +63)
    const int baser = t0 - s0 + SS - 1 - 63;
    for (int idx = tid; idx < 127 * 16; idx += 256) {
        int row = idx >> 4, c = (idx & 15) << 2;
        *(float4*)&rs[row][c] = *(const float4*)&rel[(size_t)(baser + row) * DH + c];
    }
    __syncthreads();

    float accC[4][4], accP[4][4];
#pragma unroll
    for (int i = 0; i < 4; i++)
#pragma unroll
        for (int j = 0; j < 4; j++) { accC[i][j] = 0.f; accP[i][j] = 0.f; }

    const int rbase = tx - ty + 15;   // rel row for (j-i) = -3 is rbase + 0
#pragma unroll
    for (int d0 = 0; d0 < 64; d0 += 4) {
        float a_[4][4], kv_[4][4], rl_[7][4];
#pragma unroll
        for (int i = 0; i < 4; i++) {
            float4 t = *(const float4*)&qs[ty + 16*i][d0];
            a_[i][0] = t.x; a_[i][1] = t.y; a_[i][2] = t.z; a_[i][3] = t.w;
        }
#pragma unroll
        for (int j = 0; j < 4; j++) {
            float4 t = *(const float4*)&ks[tx + 16*j][d0];
            kv_[j][0] = t.x; kv_[j][1] = t.y; kv_[j][2] = t.z; kv_[j][3] = t.w;
        }
#pragma unroll
        for (int m = 0; m < 7; m++) {
            float4 t = *(const float4*)&rs[rbase + 16*m][d0];
            rl_[m][0] = t.x; rl_[m][1] = t.y; rl_[m][2] = t.z; rl_[m][3] = t.w;
        }
#pragma unroll
        for (int c = 0; c < 4; c++)
#pragma unroll
            for (int i = 0; i < 4; i++)
#pragma unroll
                for (int j = 0; j < 4; j++) {
                    accC[i][j] += a_[i][c] * kv_[j][c];
                    accP[i][j] += a_[i][c] * rl_[j - i + 3][c];
                }
    }

#pragma unroll
    for (int i = 0; i < 4; i++)
#pragma unroll
        for (int j = 0; j < 4; j++) {
            int s = s0 + ty + 16*i, t = t0 + tx + 16*j;
            size_t o = ((size_t)z * SS + s) * SS + t;
            outc[o] = accC[i][j];
            outp[o] = accP[i][j];
        }
}

// ---------------------------------------------------------------------------
// Softmax over rows of (content + pos) / sqrt(D). One block per row.
// ---------------------------------------------------------------------------
__global__ void softmax_kernel(const float* __restrict__ outc, const float* __restrict__ outp,
                               float* __restrict__ attn) {
    const size_t row = blockIdx.x;
    const float* c = outc + row * SS;
    const float* p = outp + row * SS;
    const int tid = threadIdx.x;
    const int lane = tid & 31, wid = tid >> 5;
    const float scale = 0.044194173824159216f; // 1/sqrt(512)

    float v[4], m = -3.4e38f;
#pragma unroll
    for (int u = 0; u < 4; u++) {
        int t = tid + 256 * u;
        v[u] = (c[t] + p[t]) * scale;
        m = fmaxf(m, v[u]);
    }
#pragma unroll
    for (int o = 16; o > 0; o >>= 1) m = fmaxf(m, __shfl_xor_sync(0xffffffffu, m, o));
    __shared__ float redm[8], reds[8];
    if (lane == 0) redm[wid] = m;
    __syncthreads();
    if (tid == 0) {
        float mm = redm[0];
#pragma unroll
        for (int i = 1; i < 8; i++) mm = fmaxf(mm, redm[i]);
        redm[0] = mm;
    }
    __syncthreads();
    m = redm[0];

    float s = 0.f;
#pragma unroll
    for (int u = 0; u < 4; u++) { v[u] = __expf(v[u] - m); s += v[u]; }
#pragma unroll
    for (int o = 16; o > 0; o >>= 1) s += __shfl_xor_sync(0xffffffffu, s, o);
    if (lane == 0) reds[wid] = s;
    __syncthreads();
    if (tid == 0) {
        float ss = 0.f;
#pragma unroll
        for (int i = 0; i < 8; i++) ss += reds[i];
        reds[0] = ss;
    }
    __syncthreads();
    const float inv = 1.f / reds[0];
#pragma unroll
    for (int u = 0; u < 4; u++) attn[row * SS + tid + 256 * u] = v[u] * inv;
}

// ---------------------------------------------------------------------------
// out_h[b,s,h*64+d] = sum_t attn[z,s,t] * v[b,t,h*64+d]
// Block = 64 s-rows x full dh=64 for one z. V transposed into smem at load
// time so the inner loop is all LDS.128 along t.
// ---------------------------------------------------------------------------
__global__ void av_kernel(const float* __restrict__ attn, const float* __restrict__ Vp,
                          float* __restrict__ Oh) {
    __shared__ float as_[64][68];
    __shared__ float vsT[64][68];   // [dh][t]
    const int z = blockIdx.y;
    const int b = z >> 3, h = z & 7;
    const int s0 = blockIdx.x * 64;
    const int tid = threadIdx.x, tx = tid & 15, ty = tid >> 4;

    float acc[4][4];
#pragma unroll
    for (int i = 0; i < 4; i++)
#pragma unroll
        for (int j = 0; j < 4; j++) acc[i][j] = 0.f;

    for (int t0 = 0; t0 < SS; t0 += 64) {
#pragma unroll
        for (int it = 0; it < 4; it++) {
            int idx = tid + 256 * it;
            // attn tile: row-major STS.128
            int row = idx >> 4, c = (idx & 15) << 2;
            *(float4*)&as_[row][c] =
                *(const float4*)&attn[((size_t)z * SS + s0 + row) * SS + t0 + c];
            // V tile transposed: row-varying mapping -> conflict-free STS scatter
            int trow = idx & 63, cb = (idx >> 6) << 2;
            float4 v4 = *(const float4*)&Vp[((size_t)(b * SS + t0 + trow)) * DDIM + h * DH + cb];
            vsT[cb + 0][trow] = v4.x;
            vsT[cb + 1][trow] = v4.y;
            vsT[cb + 2][trow] = v4.z;
            vsT[cb + 3][trow] = v4.w;
        }
        __syncthreads();
#pragma unroll
        for (int tt0 = 0; tt0 < 64; tt0 += 4) {
            float a_[4][4], v_[4][4];
#pragma unroll
            for (int i = 0; i < 4; i++) {
                float4 t = *(const float4*)&as_[ty + 16*i][tt0];
                a_[i][0] = t.x; a_[i][1] = t.y; a_[i][2] = t.z; a_[i][3] = t.w;
            }
#pragma unroll
            for (int j = 0; j < 4; j++) {
                float4 t = *(const float4*)&vsT[tx + 16*j][tt0];
                v_[j][0] = t.x; v_[j][1] = t.y; v_[j][2] = t.z; v_[j][3] = t.w;
            }
#pragma unroll
            for (int c = 0; c < 4; c++)
#pragma unroll
                for (int i = 0; i < 4; i++)
#pragma unroll
                    for (int j = 0; j < 4; j++) acc[i][j] += a_[i][c] * v_[j][c];
        }
        __syncthreads();
    }
#pragma unroll
    for (int i = 0; i < 4; i++)
#pragma unroll
        for (int j = 0; j < 4; j++)
            Oh[((size_t)(b * SS + s0 + ty + 16*i)) * DDIM + h * DH + tx + 16*j] = acc[i][j];
}

// ---------------------------------------------------------------------------
extern "C" void kernel_launch(void* const* d_in, const int* in_sizes, int n_in,
                              void* d_out, int out_size) {
    const float* query   = (const float*)d_in[0];
    const float* key     = (const float*)d_in[1];
    const float* value   = (const float*)d_in[2];
    const float* pos_emb = (const float*)d_in[3];
    const float* Wq = (const float*)d_in[4];
    const float* bq = (const float*)d_in[5];
    const float* Wk = (const float*)d_in[6];
    const float* bk = (const float*)d_in[7];
    const float* Wv = (const float*)d_in[8];
    const float* bv = (const float*)d_in[9];
    const float* Wo = (const float*)d_in[10];
    const float* bo = (const float*)d_in[11];
    const float* Wp = (const float*)d_in[12];
    const float* bp = (const float*)d_in[13];
    float* out = (float*)d_out;

    float *gq, *gk, *gv, *goh, *grel;
    cudaGetSymbolAddress((void**)&gq, g_q);
    cudaGetSymbolAddress((void**)&gk, g_k);
    cudaGetSymbolAddress((void**)&gv, g_v);
    cudaGetSymbolAddress((void**)&goh, g_oh);
    cudaGetSymbolAddress((void**)&grel, g_rel);

    const int score_smem = (2 * 64 + 127) * 68 * (int)sizeof(float); // 69360 B
    cudaFuncSetAttribute(score_kernel, cudaFuncAttributeMaxDynamicSharedMemorySize, score_smem);

    dim3 gproj(DDIM / 64, (BB * SS) / 64);   // (8, 64)
    proj_gemm<<<gproj, 256>>>(query, Wq, bq, gq);
    proj_gemm<<<gproj, 256>>>(key,   Wk, bk, gk);
    proj_gemm<<<gproj, 256>>>(value, Wv, bv, gv);
    rel_proj<<<RP, DH>>>(pos_emb, Wp, bp, grel);

    score_kernel<<<dim3(SS / 64, SS / 64, BB * HH), 256, score_smem>>>(
        gq, gk, grel, out + OFF_CONTENT, out + OFF_POS);

    softmax_kernel<<<BB * HH * SS, 256>>>(out + OFF_CONTENT, out + OFF_POS, out + OFF_ATTN);

    av_kernel<<<dim3(SS / 64, BB * HH), 256>>>(out + OFF_ATTN, gv, goh);

    proj_gemm<<<gproj, 256>>>(goh, Wo, bo, out);
}

// round 6
// speedup vs baseline: 1.1211x; 1.0375x over previous
#include <cuda_runtime.h>

#define BB 4
#define SS 1024
#define DDIM 512
#define HH 8
#define DH 64
#define RP (2*SS-1)   // 2047

// Output layout (tuple concatenated, float32):
//   out      [B,S,D]      @ 0
//   attn     [B,H,S,S]    @ OFF_ATTN
//   content  [B,H,S,S]    @ OFF_CONTENT
//   pos      [B,H,S,S]    @ OFF_POS   (already relative-shifted)
#define N_OUT  ((size_t)BB*SS*DDIM)          // 2,097,152
#define N_SC   ((size_t)BB*HH*SS*SS)         // 33,554,432
#define OFF_ATTN     (N_OUT)
#define OFF_CONTENT  (N_OUT + N_SC)
#define OFF_POS      (N_OUT + 2*N_SC)

// Scratch (allocation-free: device globals)
__device__ float g_q[BB*SS*DDIM];
__device__ float g_k[BB*SS*DDIM];
__device__ float g_v[BB*SS*DDIM];
__device__ float g_oh[BB*SS*DDIM];
__device__ float g_rel[RP*DH];

// Packed f32x2 FMA (Blackwell FFMA2): d = a*b + d, elementwise on 2 lanes.
__device__ __forceinline__ void ffma2(float2& d, const float2& a, const float2& b) {
    asm("fma.rn.f32x2 %0, %1, %2, %0;"
        : "+l"(reinterpret_cast<unsigned long long&>(d))
        : "l"(reinterpret_cast<const unsigned long long&>(a)),
          "l"(reinterpret_cast<const unsigned long long&>(b)));
}

// ---------------------------------------------------------------------------
// C[M,N] = A[M,K] @ W[N,K]^T + bias     (M=4096, N=512, K=512)
// 64x64 block tile, 256 threads, 4x4 micro-tile, f32x2 packed accumulation.
// ---------------------------------------------------------------------------
__global__ void proj_gemm(const float* __restrict__ A, const float* __restrict__ W,
                          const float* __restrict__ bias, float* __restrict__ C) {
    const int K = DDIM, N = DDIM;
    __shared__ float As[64][20];
    __shared__ float Ws[64][20];
    const int tid = threadIdx.x;
    const int tx = tid & 15, ty = tid >> 4;
    const int m0 = blockIdx.y * 64, n0 = blockIdx.x * 64;
    const int lrow = tid >> 2, lq = (tid & 3) << 2;

    float2 acc[4][4];
#pragma unroll
    for (int i = 0; i < 4; i++)
#pragma unroll
        for (int j = 0; j < 4; j++) acc[i][j] = make_float2(0.f, 0.f);

    for (int k0 = 0; k0 < K; k0 += 16) {
        float4 a4 = *(const float4*)&A[(size_t)(m0 + lrow) * K + k0 + lq];
        float4 w4 = *(const float4*)&W[(size_t)(n0 + lrow) * K + k0 + lq];
        *(float4*)&As[lrow][lq] = a4;
        *(float4*)&Ws[lrow][lq] = w4;
        __syncthreads();
#pragma unroll
        for (int kk0 = 0; kk0 < 16; kk0 += 4) {
            float4 af[4], wf[4];
#pragma unroll
            for (int i = 0; i < 4; i++) af[i] = *(const float4*)&As[ty + 16*i][kk0];
#pragma unroll
            for (int j = 0; j < 4; j++) wf[j] = *(const float4*)&Ws[tx + 16*j][kk0];
#pragma unroll
            for (int cp = 0; cp < 2; cp++) {
                float2 a2[4], w2[4];
#pragma unroll
                for (int i = 0; i < 4; i++)
                    a2[i] = cp ? make_float2(af[i].z, af[i].w) : make_float2(af[i].x, af[i].y);
#pragma unroll
                for (int j = 0; j < 4; j++)
                    w2[j] = cp ? make_float2(wf[j].z, wf[j].w) : make_float2(wf[j].x, wf[j].y);
#pragma unroll
                for (int i = 0; i < 4; i++)
#pragma unroll
                    for (int j = 0; j < 4; j++) ffma2(acc[i][j], a2[i], w2[j]);
            }
        }
        __syncthreads();
    }
#pragma unroll
    for (int i = 0; i < 4; i++)
#pragma unroll
        for (int j = 0; j < 4; j++) {
            int m = m0 + ty + 16*i, n = n0 + tx + 16*j;
            C[(size_t)m * N + n] = acc[i][j].x + acc[i][j].y + bias[n];
        }
}

// ---------------------------------------------------------------------------
// rel[r,n] = sum_k pos_emb[r,k] * Wp[n,k] + bp[n]   (r<2047, n,k<64)
// ---------------------------------------------------------------------------
__global__ void rel_proj(const float* __restrict__ pos_emb, const float* __restrict__ Wp,
                         const float* __restrict__ bp, float* __restrict__ rel) {
    __shared__ float pe[DH];
    __shared__ float wps[DH][DH + 1];
    const int r = blockIdx.x;
    const int tid = threadIdx.x;
    pe[tid] = pos_emb[(size_t)r * DH + tid];
#pragma unroll
    for (int j = 0; j < DH; j++) wps[j][tid] = Wp[(size_t)j * DH + tid];
    __syncthreads();
    float acc = bp[tid];
#pragma unroll 8
    for (int k = 0; k < DH; k++) acc += pe[k] * wps[tid][k];
    rel[(size_t)r * DH + tid] = acc;
}

// ---------------------------------------------------------------------------
// Fused content + (pre-shifted) positional score.
//   content[z,s,t] = sum_d q[z,s,d]*k[z,t,d]
//   pos[z,s,t]     = sum_d q[z,s,d]*rel[t-s+S-1,d]   (skew trick collapsed)
// Block = 64x64 (s,t) tile for one z=(b,h). f32x2 packed accumulation.
// ---------------------------------------------------------------------------
__global__ void __launch_bounds__(256, 2)
score_kernel(const float* __restrict__ Qp, const float* __restrict__ Kp,
             const float* __restrict__ rel,
             float* __restrict__ outc, float* __restrict__ outp) {
    extern __shared__ float sm[];
    float (*qs)[68] = (float(*)[68])sm;
    float (*ks)[68] = (float(*)[68])(sm + 64 * 68);
    float (*rs)[68] = (float(*)[68])(sm + 2 * 64 * 68);

    const int z = blockIdx.z;
    const int b = z >> 3, h = z & 7;
    const int s0 = blockIdx.y * 64, t0 = blockIdx.x * 64;
    const int tid = threadIdx.x, tx = tid & 15, ty = tid >> 4;

    // load q, k tiles: 64 rows x 64 floats each (STS.128, coalesced)
#pragma unroll
    for (int it = 0; it < 4; it++) {
        int idx = tid + 256 * it;
        int row = idx >> 4, c = (idx & 15) << 2;
        *(float4*)&qs[row][c] =
            *(const float4*)&Qp[((size_t)(b * SS + s0 + row)) * DDIM + h * DH + c];
        *(float4*)&ks[row][c] =
            *(const float4*)&Kp[((size_t)(b * SS + t0 + row)) * DDIM + h * DH + c];
    }
    // rel window: rows baser .. baser+126  (= t0-s0+S-1-63 ... +63)
    const int baser = t0 - s0 + SS - 1 - 63;
    for (int idx = tid; idx < 127 * 16; idx += 256) {
        int row = idx >> 4, c = (idx & 15) << 2;
        *(float4*)&rs[row][c] = *(const float4*)&rel[(size_t)(baser + row) * DH + c];
    }
    __syncthreads();

    float2 accC[4][4], accP[4][4];
#pragma unroll
    for (int i = 0; i < 4; i++)
#pragma unroll
        for (int j = 0; j < 4; j++) {
            accC[i][j] = make_float2(0.f, 0.f);
            accP[i][j] = make_float2(0.f, 0.f);
        }

    const int rbase = tx - ty + 15;   // rel row for (j-i) = -3 is rbase + 0
#pragma unroll
    for (int d0 = 0; d0 < 64; d0 += 4) {
        float4 aq[4], kk[4];
#pragma unroll
        for (int i = 0; i < 4; i++) aq[i] = *(const float4*)&qs[ty + 16*i][d0];
#pragma unroll
        for (int j = 0; j < 4; j++) kk[j] = *(const float4*)&ks[tx + 16*j][d0];
#pragma unroll
        for (int cp = 0; cp < 2; cp++) {
            float2 a2[4], k2[4], r2[7];
#pragma unroll
            for (int i = 0; i < 4; i++)
                a2[i] = cp ? make_float2(aq[i].z, aq[i].w) : make_float2(aq[i].x, aq[i].y);
#pragma unroll
            for (int j = 0; j < 4; j++)
                k2[j] = cp ? make_float2(kk[j].z, kk[j].w) : make_float2(kk[j].x, kk[j].y);
#pragma unroll
            for (int m = 0; m < 7; m++)
                r2[m] = *(const float2*)&rs[rbase + 16*m][d0 + 2*cp];
#pragma unroll
            for (int i = 0; i < 4; i++)
#pragma unroll
                for (int j = 0; j < 4; j++) {
                    ffma2(accC[i][j], a2[i], k2[j]);
                    ffma2(accP[i][j], a2[i], r2[j - i + 3]);
                }
        }
    }

#pragma unroll
    for (int i = 0; i < 4; i++)
#pragma unroll
        for (int j = 0; j < 4; j++) {
            int s = s0 + ty + 16*i, t = t0 + tx + 16*j;
            size_t o = ((size_t)z * SS + s) * SS + t;
            outc[o] = accC[i][j].x + accC[i][j].y;
            outp[o] = accP[i][j].x + accP[i][j].y;
        }
}

// ---------------------------------------------------------------------------
// Softmax over rows of (content + pos) / sqrt(D). One block per row.
// ---------------------------------------------------------------------------
__global__ void softmax_kernel(const float* __restrict__ outc, const float* __restrict__ outp,
                               float* __restrict__ attn) {
    const size_t row = blockIdx.x;
    const float* c = outc + row * SS;
    const float* p = outp + row * SS;
    const int tid = threadIdx.x;
    const int lane = tid & 31, wid = tid >> 5;
    const float scale = 0.044194173824159216f; // 1/sqrt(512)

    float v[4], m = -3.4e38f;
#pragma unroll
    for (int u = 0; u < 4; u++) {
        int t = tid + 256 * u;
        v[u] = (c[t] + p[t]) * scale;
        m = fmaxf(m, v[u]);
    }
#pragma unroll
    for (int o = 16; o > 0; o >>= 1) m = fmaxf(m, __shfl_xor_sync(0xffffffffu, m, o));
    __shared__ float redm[8], reds[8];
    if (lane == 0) redm[wid] = m;
    __syncthreads();
    if (tid == 0) {
        float mm = redm[0];
#pragma unroll
        for (int i = 1; i < 8; i++) mm = fmaxf(mm, redm[i]);
        redm[0] = mm;
    }
    __syncthreads();
    m = redm[0];

    float s = 0.f;
#pragma unroll
    for (int u = 0; u < 4; u++) { v[u] = __expf(v[u] - m); s += v[u]; }
#pragma unroll
    for (int o = 16; o > 0; o >>= 1) s += __shfl_xor_sync(0xffffffffu, s, o);
    if (lane == 0) reds[wid] = s;
    __syncthreads();
    if (tid == 0) {
        float ss = 0.f;
#pragma unroll
        for (int i = 0; i < 8; i++) ss += reds[i];
        reds[0] = ss;
    }
    __syncthreads();
    const float inv = 1.f / reds[0];
#pragma unroll
    for (int u = 0; u < 4; u++) attn[row * SS + tid + 256 * u] = v[u] * inv;
}

// ---------------------------------------------------------------------------
// out_h[b,s,h*64+d] = sum_t attn[z,s,t] * v[b,t,h*64+d]
// Block = 64 s-rows x full dh=64 for one z. V transposed into smem at load
// time; f32x2 packed accumulation along t.
// ---------------------------------------------------------------------------
__global__ void av_kernel(const float* __restrict__ attn, const float* __restrict__ Vp,
                          float* __restrict__ Oh) {
    __shared__ float as_[64][68];
    __shared__ float vsT[64][68];   // [dh][t]
    const int z = blockIdx.y;
    const int b = z >> 3, h = z & 7;
    const int s0 = blockIdx.x * 64;
    const int tid = threadIdx.x, tx = tid & 15, ty = tid >> 4;

    float2 acc[4][4];
#pragma unroll
    for (int i = 0; i < 4; i++)
#pragma unroll
        for (int j = 0; j < 4; j++) acc[i][j] = make_float2(0.f, 0.f);

    for (int t0 = 0; t0 < SS; t0 += 64) {
#pragma unroll
        for (int it = 0; it < 4; it++) {
            int idx = tid + 256 * it;
            // attn tile: row-major STS.128
            int row = idx >> 4, c = (idx & 15) << 2;
            *(float4*)&as_[row][c] =
                *(const float4*)&attn[((size_t)z * SS + s0 + row) * SS + t0 + c];
            // V tile transposed: row-varying mapping -> conflict-free STS scatter
            int trow = idx & 63, cb = (idx >> 6) << 2;
            float4 v4 = *(const float4*)&Vp[((size_t)(b * SS + t0 + trow)) * DDIM + h * DH + cb];
            vsT[cb + 0][trow] = v4.x;
            vsT[cb + 1][trow] = v4.y;
            vsT[cb + 2][trow] = v4.z;
            vsT[cb + 3][trow] = v4.w;
        }
        __syncthreads();
#pragma unroll
        for (int tt0 = 0; tt0 < 64; tt0 += 4) {
            float4 af[4], vf[4];
#pragma unroll
            for (int i = 0; i < 4; i++) af[i] = *(const float4*)&as_[ty + 16*i][tt0];
#pragma unroll
            for (int j = 0; j < 4; j++) vf[j] = *(const float4*)&vsT[tx + 16*j][tt0];
#pragma unroll
            for (int cp = 0; cp < 2; cp++) {
                float2 a2[4], v2[4];
#pragma unroll
                for (int i = 0; i < 4; i++)
                    a2[i] = cp ? make_float2(af[i].z, af[i].w) : make_float2(af[i].x, af[i].y);
#pragma unroll
                for (int j = 0; j < 4; j++)
                    v2[j] = cp ? make_float2(vf[j].z, vf[j].w) : make_float2(vf[j].x, vf[j].y);
#pragma unroll
                for (int i = 0; i < 4; i++)
#pragma unroll
                    for (int j = 0; j < 4; j++) ffma2(acc[i][j], a2[i], v2[j]);
            }
        }
        __syncthreads();
    }
#pragma unroll
    for (int i = 0; i < 4; i++)
#pragma unroll
        for (int j = 0; j < 4; j++)
            Oh[((size_t)(b * SS + s0 + ty + 16*i)) * DDIM + h * DH + tx + 16*j] =
                acc[i][j].x + acc[i][j].y;
}

// ---------------------------------------------------------------------------
extern "C" void kernel_launch(void* const* d_in, const int* in_sizes, int n_in,
                              void* d_out, int out_size) {
    const float* query   = (const float*)d_in[0];
    const float* key     = (const float*)d_in[1];
    const float* value   = (const float*)d_in[2];
    const float* pos_emb = (const float*)d_in[3];
    const float* Wq = (const float*)d_in[4];
    const float* bq = (const float*)d_in[5];
    const float* Wk = (const float*)d_in[6];
    const float* bk = (const float*)d_in[7];
    const float* Wv = (const float*)d_in[8];
    const float* bv = (const float*)d_in[9];
    const float* Wo = (const float*)d_in[10];
    const float* bo = (const float*)d_in[11];
    const float* Wp = (const float*)d_in[12];
    const float* bp = (const float*)d_in[13];
    float* out = (float*)d_out;

    float *gq, *gk, *gv, *goh, *grel;
    cudaGetSymbolAddress((void**)&gq, g_q);
    cudaGetSymbolAddress((void**)&gk, g_k);
    cudaGetSymbolAddress((void**)&gv, g_v);
    cudaGetSymbolAddress((void**)&goh, g_oh);
    cudaGetSymbolAddress((void**)&grel, g_rel);

    const int score_smem = (2 * 64 + 127) * 68 * (int)sizeof(float); // 69360 B
    cudaFuncSetAttribute(score_kernel, cudaFuncAttributeMaxDynamicSharedMemorySize, score_smem);

    dim3 gproj(DDIM / 64, (BB * SS) / 64);   // (8, 64)
    proj_gemm<<<gproj, 256>>>(query, Wq, bq, gq);
    proj_gemm<<<gproj, 256>>>(key,   Wk, bk, gk);
    proj_gemm<<<gproj, 256>>>(value, Wv, bv, gv);
    rel_proj<<<RP, DH>>>(pos_emb, Wp, bp, grel);

    score_kernel<<<dim3(SS / 64, SS / 64, BB * HH), 256, score_smem>>>(
        gq, gk, grel, out + OFF_CONTENT, out + OFF_POS);

    softmax_kernel<<<BB * HH * SS, 256>>>(out + OFF_CONTENT, out + OFF_POS, out + OFF_ATTN);

    av_kernel<<<dim3(SS / 64, BB * HH), 256>>>(out + OFF_ATTN, gv, goh);

    proj_gemm<<<gproj, 256>>>(goh, Wo, bo, out);
}

// round 7
// speedup vs baseline: 1.3071x; 1.1659x over previous
#include <cuda_runtime.h>

#define BB 4
#define SS 1024
#define DDIM 512
#define HH 8
#define DH 64
#define RP (2*SS-1)   // 2047

// Output layout (tuple concatenated, float32):
//   out      [B,S,D]      @ 0
//   attn     [B,H,S,S]    @ OFF_ATTN
//   content  [B,H,S,S]    @ OFF_CONTENT
//   pos      [B,H,S,S]    @ OFF_POS   (already relative-shifted)
#define N_OUT  ((size_t)BB*SS*DDIM)
#define N_SC   ((size_t)BB*HH*SS*SS)
#define OFF_ATTN     (N_OUT)
#define OFF_CONTENT  (N_OUT + N_SC)
#define OFF_POS      (N_OUT + 2*N_SC)

// Scratch (allocation-free: device globals)
__device__ float g_q[BB*SS*DDIM];
__device__ float g_k[BB*SS*DDIM];
__device__ float g_v[BB*SS*DDIM];
__device__ float g_oh[BB*SS*DDIM];
__device__ float g_rel[RP*DH];

// Packed f32x2 FMA (Blackwell FFMA2): d = a*b + d, elementwise on 2 lanes.
__device__ __forceinline__ void ffma2(float2& d, const float2& a, const float2& b) {
    asm("fma.rn.f32x2 %0, %1, %2, %0;"
        : "+l"(reinterpret_cast<unsigned long long&>(d))
        : "l"(reinterpret_cast<const unsigned long long&>(a)),
          "l"(reinterpret_cast<const unsigned long long&>(b)));
}

// ---------------------------------------------------------------------------
// C[M,N] = A[M,K] @ W[N,K]^T + bias     (M=4096, N=512, K=512)
// 128x128 block tile, 256 threads, 8x8 micro-tile, f32x2 packed.
// Register double-buffered gmem slab loads (1 block/SM).
// ---------------------------------------------------------------------------
__global__ void __launch_bounds__(256, 1)
proj_gemm(const float* __restrict__ A, const float* __restrict__ W,
          const float* __restrict__ bias, float* __restrict__ C) {
    const int K = DDIM, N = DDIM;
    __shared__ float As[128][20];
    __shared__ float Ws[128][20];
    const int tid = threadIdx.x;
    const int tx = tid & 15, ty = tid >> 4;
    const int m0 = blockIdx.y * 128, n0 = blockIdx.x * 128;

    float2 acc[8][8];
#pragma unroll
    for (int i = 0; i < 8; i++)
#pragma unroll
        for (int j = 0; j < 8; j++) acc[i][j] = make_float2(0.f, 0.f);

    float4 pa[2], pw[2];
#pragma unroll
    for (int it = 0; it < 2; it++) {
        int idx = tid + 256 * it, row = idx >> 2, q = (idx & 3) << 2;
        pa[it] = *(const float4*)&A[(size_t)(m0 + row) * K + q];
        pw[it] = *(const float4*)&W[(size_t)(n0 + row) * K + q];
    }

    for (int k0 = 0; k0 < K; k0 += 16) {
#pragma unroll
        for (int it = 0; it < 2; it++) {
            int idx = tid + 256 * it, row = idx >> 2, q = (idx & 3) << 2;
            *(float4*)&As[row][q] = pa[it];
            *(float4*)&Ws[row][q] = pw[it];
        }
        __syncthreads();
        if (k0 + 16 < K) {
#pragma unroll
            for (int it = 0; it < 2; it++) {
                int idx = tid + 256 * it, row = idx >> 2, q = (idx & 3) << 2;
                pa[it] = *(const float4*)&A[(size_t)(m0 + row) * K + k0 + 16 + q];
                pw[it] = *(const float4*)&W[(size_t)(n0 + row) * K + k0 + 16 + q];
            }
        }
#pragma unroll
        for (int kk0 = 0; kk0 < 16; kk0 += 4) {
            float4 af[8];
#pragma unroll
            for (int i = 0; i < 8; i++) af[i] = *(const float4*)&As[ty + 16*i][kk0];
#pragma unroll
            for (int j = 0; j < 8; j++) {
                float4 wf = *(const float4*)&Ws[tx + 16*j][kk0];
                float2 wa = make_float2(wf.x, wf.y), wb = make_float2(wf.z, wf.w);
#pragma unroll
                for (int i = 0; i < 8; i++) {
                    float2 aa = make_float2(af[i].x, af[i].y);
                    float2 ab = make_float2(af[i].z, af[i].w);
                    ffma2(acc[i][j], aa, wa);
                    ffma2(acc[i][j], ab, wb);
                }
            }
        }
        __syncthreads();
    }
#pragma unroll
    for (int i = 0; i < 8; i++)
#pragma unroll
        for (int j = 0; j < 8; j++) {
            int m = m0 + ty + 16*i, n = n0 + tx + 16*j;
            C[(size_t)m * N + n] = acc[i][j].x + acc[i][j].y + bias[n];
        }
}

// ---------------------------------------------------------------------------
// rel[r,n] = sum_k pos_emb[r,k] * Wp[n,k] + bp[n]   (r<2047, n,k<64)
// ---------------------------------------------------------------------------
__global__ void rel_proj(const float* __restrict__ pos_emb, const float* __restrict__ Wp,
                         const float* __restrict__ bp, float* __restrict__ rel) {
    __shared__ float pe[DH];
    __shared__ float wps[DH][DH + 1];
    const int r = blockIdx.x;
    const int tid = threadIdx.x;
    pe[tid] = pos_emb[(size_t)r * DH + tid];
#pragma unroll
    for (int j = 0; j < DH; j++) wps[j][tid] = Wp[(size_t)j * DH + tid];
    __syncthreads();
    float acc = bp[tid];
#pragma unroll 8
    for (int k = 0; k < DH; k++) acc += pe[k] * wps[tid][k];
    rel[(size_t)r * DH + tid] = acc;
}

// ---------------------------------------------------------------------------
// content[z,s,t] = sum_d q[z,s,d]*k[z,t,d]
// Block = 128x128 (s,t) tile for one z=(b,h), 8x8 micro, f32x2 packed.
// ---------------------------------------------------------------------------
__global__ void __launch_bounds__(256, 1)
content_kernel(const float* __restrict__ Qp, const float* __restrict__ Kp,
               float* __restrict__ outc) {
    extern __shared__ float sm[];
    float (*qs)[68] = (float(*)[68])sm;
    float (*ks)[68] = (float(*)[68])(sm + 128 * 68);

    const int z = blockIdx.z;
    const int b = z >> 3, h = z & 7;
    const int s0 = blockIdx.y * 128, t0 = blockIdx.x * 128;
    const int tid = threadIdx.x, tx = tid & 15, ty = tid >> 4;

#pragma unroll
    for (int it = 0; it < 8; it++) {
        int idx = tid + 256 * it, row = idx >> 4, c = (idx & 15) << 2;
        *(float4*)&qs[row][c] =
            *(const float4*)&Qp[((size_t)(b * SS + s0 + row)) * DDIM + h * DH + c];
        *(float4*)&ks[row][c] =
            *(const float4*)&Kp[((size_t)(b * SS + t0 + row)) * DDIM + h * DH + c];
    }
    __syncthreads();

    float2 acc[8][8];
#pragma unroll
    for (int i = 0; i < 8; i++)
#pragma unroll
        for (int j = 0; j < 8; j++) acc[i][j] = make_float2(0.f, 0.f);

#pragma unroll 4
    for (int d0 = 0; d0 < 64; d0 += 4) {
        float4 af[8];
#pragma unroll
        for (int i = 0; i < 8; i++) af[i] = *(const float4*)&qs[ty + 16*i][d0];
#pragma unroll
        for (int j = 0; j < 8; j++) {
            float4 kf = *(const float4*)&ks[tx + 16*j][d0];
            float2 ka = make_float2(kf.x, kf.y), kb = make_float2(kf.z, kf.w);
#pragma unroll
            for (int i = 0; i < 8; i++) {
                float2 aa = make_float2(af[i].x, af[i].y);
                float2 ab = make_float2(af[i].z, af[i].w);
                ffma2(acc[i][j], aa, ka);
                ffma2(acc[i][j], ab, kb);
            }
        }
    }

#pragma unroll
    for (int i = 0; i < 8; i++)
#pragma unroll
        for (int j = 0; j < 8; j++) {
            int s = s0 + ty + 16*i, t = t0 + tx + 16*j;
            outc[((size_t)z * SS + s) * SS + t] = acc[i][j].x + acc[i][j].y;
        }
}

// ---------------------------------------------------------------------------
// pos[z,s,t] = sum_d q[z,s,d]*rel[t-s+S-1,d]   (skew collapsed)
// Block = 128x128 tile; rel window 255 rows. 8x8 micro, f32x2 packed.
// rel fragment streamed one diagonal class at a time (15 per chunk).
// ---------------------------------------------------------------------------
__global__ void __launch_bounds__(256, 1)
pos_kernel(const float* __restrict__ Qp, const float* __restrict__ rel,
           float* __restrict__ outp) {
    extern __shared__ float sm[];
    float (*qs)[68] = (float(*)[68])sm;
    float (*rs)[68] = (float(*)[68])(sm + 128 * 68);

    const int z = blockIdx.z;
    const int b = z >> 3, h = z & 7;
    const int s0 = blockIdx.y * 128, t0 = blockIdx.x * 128;
    const int tid = threadIdx.x, tx = tid & 15, ty = tid >> 4;

#pragma unroll
    for (int it = 0; it < 8; it++) {
        int idx = tid + 256 * it, row = idx >> 4, c = (idx & 15) << 2;
        *(float4*)&qs[row][c] =
            *(const float4*)&Qp[((size_t)(b * SS + s0 + row)) * DDIM + h * DH + c];
    }
    // rel window rows baser .. baser+254 ; baser = t0-s0+S-1-127, in-bounds
    const int baser = t0 - s0 + SS - 1 - 127;
    for (int idx = tid; idx < 255 * 16; idx += 256) {
        int row = idx >> 4, c = (idx & 15) << 2;
        *(float4*)&rs[row][c] = *(const float4*)&rel[(size_t)(baser + row) * DH + c];
    }
    __syncthreads();

    float2 acc[8][8];
#pragma unroll
    for (int i = 0; i < 8; i++)
#pragma unroll
        for (int j = 0; j < 8; j++) acc[i][j] = make_float2(0.f, 0.f);

    const int rbase = tx - ty + 15;  // smem row for diagonal class m=0
#pragma unroll 4
    for (int d0 = 0; d0 < 64; d0 += 4) {
        float4 af[8];
#pragma unroll
        for (int i = 0; i < 8; i++) af[i] = *(const float4*)&qs[ty + 16*i][d0];
#pragma unroll
        for (int m = 0; m < 15; m++) {
            float4 r4 = *(const float4*)&rs[rbase + 16*m][d0];
            float2 ra = make_float2(r4.x, r4.y), rb = make_float2(r4.z, r4.w);
#pragma unroll
            for (int i = 0; i < 8; i++) {
                int j = m - 7 + i;
                if (j >= 0 && j < 8) {
                    float2 aa = make_float2(af[i].x, af[i].y);
                    float2 ab = make_float2(af[i].z, af[i].w);
                    ffma2(acc[i][j], aa, ra);
                    ffma2(acc[i][j], ab, rb);
                }
            }
        }
    }

#pragma unroll
    for (int i = 0; i < 8; i++)
#pragma unroll
        for (int j = 0; j < 8; j++) {
            int s = s0 + ty + 16*i, t = t0 + tx + 16*j;
            outp[((size_t)z * SS + s) * SS + t] = acc[i][j].x + acc[i][j].y;
        }
}

// ---------------------------------------------------------------------------
// Softmax over rows of (content + pos) / sqrt(D). One block per row, float4.
// ---------------------------------------------------------------------------
__global__ void softmax_kernel(const float* __restrict__ outc, const float* __restrict__ outp,
                               float* __restrict__ attn) {
    const size_t row = blockIdx.x;
    const float* c = outc + row * SS;
    const float* p = outp + row * SS;
    const int tid = threadIdx.x;
    const int lane = tid & 31, wid = tid >> 5;
    const float scale = 0.044194173824159216f; // 1/sqrt(512)

    float4 c4 = *(const float4*)&c[4 * tid];
    float4 p4 = *(const float4*)&p[4 * tid];
    float v[4];
    v[0] = (c4.x + p4.x) * scale; v[1] = (c4.y + p4.y) * scale;
    v[2] = (c4.z + p4.z) * scale; v[3] = (c4.w + p4.w) * scale;
    float m = fmaxf(fmaxf(v[0], v[1]), fmaxf(v[2], v[3]));
#pragma unroll
    for (int o = 16; o > 0; o >>= 1) m = fmaxf(m, __shfl_xor_sync(0xffffffffu, m, o));
    __shared__ float redm[8], reds[8];
    if (lane == 0) redm[wid] = m;
    __syncthreads();
    if (tid == 0) {
        float mm = redm[0];
#pragma unroll
        for (int i = 1; i < 8; i++) mm = fmaxf(mm, redm[i]);
        redm[0] = mm;
    }
    __syncthreads();
    m = redm[0];

    float s = 0.f;
#pragma unroll
    for (int u = 0; u < 4; u++) { v[u] = __expf(v[u] - m); s += v[u]; }
#pragma unroll
    for (int o = 16; o > 0; o >>= 1) s += __shfl_xor_sync(0xffffffffu, s, o);
    if (lane == 0) reds[wid] = s;
    __syncthreads();
    if (tid == 0) {
        float ss = 0.f;
#pragma unroll
        for (int i = 0; i < 8; i++) ss += reds[i];
        reds[0] = ss;
    }
    __syncthreads();
    const float inv = 1.f / reds[0];
    float4 o4 = make_float4(v[0] * inv, v[1] * inv, v[2] * inv, v[3] * inv);
    *(float4*)&attn[row * SS + 4 * tid] = o4;
}

// ---------------------------------------------------------------------------
// out_h[b,s,h*64+d] = sum_t attn[z,s,t] * v[b,t,h*64+d]
// Block = 128 s-rows x dh=64 for one z. 8x4 micro, f32x2 packed,
// V transposed into smem. 2 blocks/SM.
// ---------------------------------------------------------------------------
__global__ void __launch_bounds__(256, 2)
av_kernel(const float* __restrict__ attn, const float* __restrict__ Vp,
          float* __restrict__ Oh) {
    extern __shared__ float sm[];
    float (*as_)[68] = (float(*)[68])sm;            // [128 s][t]
    float (*vsT)[68] = (float(*)[68])(sm + 128 * 68); // [64 d][t]
    const int z = blockIdx.y;
    const int b = z >> 3, h = z & 7;
    const int s0 = blockIdx.x * 128;
    const int tid = threadIdx.x, tx = tid & 15, ty = tid >> 4;

    float2 acc[8][4];
#pragma unroll
    for (int i = 0; i < 8; i++)
#pragma unroll
        for (int j = 0; j < 4; j++) acc[i][j] = make_float2(0.f, 0.f);

    for (int t0 = 0; t0 < SS; t0 += 64) {
#pragma unroll
        for (int it = 0; it < 8; it++) {
            int idx = tid + 256 * it, row = idx >> 4, c = (idx & 15) << 2;
            *(float4*)&as_[row][c] =
                *(const float4*)&attn[((size_t)z * SS + s0 + row) * SS + t0 + c];
        }
#pragma unroll
        for (int it = 0; it < 4; it++) {
            int idx = tid + 256 * it;
            int trow = idx & 63, cb = (idx >> 6) << 2;
            float4 v4 = *(const float4*)&Vp[((size_t)(b * SS + t0 + trow)) * DDIM + h * DH + cb];
            vsT[cb + 0][trow] = v4.x;
            vsT[cb + 1][trow] = v4.y;
            vsT[cb + 2][trow] = v4.z;
            vsT[cb + 3][trow] = v4.w;
        }
        __syncthreads();
#pragma unroll 4
        for (int tt0 = 0; tt0 < 64; tt0 += 4) {
            float4 af[8];
#pragma unroll
            for (int i = 0; i < 8; i++) af[i] = *(const float4*)&as_[ty + 16*i][tt0];
#pragma unroll
            for (int j = 0; j < 4; j++) {
                float4 vf = *(const float4*)&vsT[tx + 16*j][tt0];
                float2 va = make_float2(vf.x, vf.y), vb = make_float2(vf.z, vf.w);
#pragma unroll
                for (int i = 0; i < 8; i++) {
                    float2 aa = make_float2(af[i].x, af[i].y);
                    float2 ab = make_float2(af[i].z, af[i].w);
                    ffma2(acc[i][j], aa, va);
                    ffma2(acc[i][j], ab, vb);
                }
            }
        }
        __syncthreads();
    }
#pragma unroll
    for (int i = 0; i < 8; i++)
#pragma unroll
        for (int j = 0; j < 4; j++)
            Oh[((size_t)(b * SS + s0 + ty + 16*i)) * DDIM + h * DH + tx + 16*j] =
                acc[i][j].x + acc[i][j].y;
}

// ---------------------------------------------------------------------------
extern "C" void kernel_launch(void* const* d_in, const int* in_sizes, int n_in,
                              void* d_out, int out_size) {
    const float* query   = (const float*)d_in[0];
    const float* key     = (const float*)d_in[1];
    const float* value   = (const float*)d_in[2];
    const float* pos_emb = (const float*)d_in[3];
    const float* Wq = (const float*)d_in[4];
    const float* bq = (const float*)d_in[5];
    const float* Wk = (const float*)d_in[6];
    const float* bk = (const float*)d_in[7];
    const float* Wv = (const float*)d_in[8];
    const float* bv = (const float*)d_in[9];
    const float* Wo = (const float*)d_in[10];
    const float* bo = (const float*)d_in[11];
    const float* Wp = (const float*)d_in[12];
    const float* bp = (const float*)d_in[13];
    float* out = (float*)d_out;

    float *gq, *gk, *gv, *goh, *grel;
    cudaGetSymbolAddress((void**)&gq, g_q);
    cudaGetSymbolAddress((void**)&gk, g_k);
    cudaGetSymbolAddress((void**)&gv, g_v);
    cudaGetSymbolAddress((void**)&goh, g_oh);
    cudaGetSymbolAddress((void**)&grel, g_rel);

    const int content_smem = 2 * 128 * 68 * (int)sizeof(float);        // 69632
    const int pos_smem     = (128 + 255) * 68 * (int)sizeof(float);    // 104176
    const int av_smem      = (128 + 64) * 68 * (int)sizeof(float);     // 52224
    cudaFuncSetAttribute(content_kernel, cudaFuncAttributeMaxDynamicSharedMemorySize, content_smem);
    cudaFuncSetAttribute(pos_kernel,     cudaFuncAttributeMaxDynamicSharedMemorySize, pos_smem);
    cudaFuncSetAttribute(av_kernel,      cudaFuncAttributeMaxDynamicSharedMemorySize, av_smem);

    dim3 gproj(DDIM / 128, (BB * SS) / 128);   // (4, 32)
    proj_gemm<<<gproj, 256>>>(query, Wq, bq, gq);
    proj_gemm<<<gproj, 256>>>(key,   Wk, bk, gk);
    proj_gemm<<<gproj, 256>>>(value, Wv, bv, gv);
    rel_proj<<<RP, DH>>>(pos_emb, Wp, bp, grel);

    content_kernel<<<dim3(SS / 128, SS / 128, BB * HH), 256, content_smem>>>(
        gq, gk, out + OFF_CONTENT);
    pos_kernel<<<dim3(SS / 128, SS / 128, BB * HH), 256, pos_smem>>>(
        gq, grel, out + OFF_POS);

    softmax_kernel<<<BB * HH * SS, 256>>>(out + OFF_CONTENT, out + OFF_POS, out + OFF_ATTN);

    av_kernel<<<dim3(SS / 128, BB * HH), 256, av_smem>>>(out + OFF_ATTN, gv, goh);

    proj_gemm<<<gproj, 256>>>(goh, Wo, bo, out);
}